// round 9
// baseline (speedup 1.0000x reference)
#include <cuda_runtime.h>
#include <cuda_bf16.h>
#include <cstdint>
#include <math.h>

// Problem constants
#define BB 64
#define SS 512
#define EE 128
#define HH 1024
#define VV 128
#define OO 128
#define NBLK 128          // GRU CTAs; each owns 8 j-columns (x3 gates = 24 weight rows)
#define HP 136            // padded row (elems) for logits kernel SMEM
#define WP 1032           // padded row (elems) for weight SMEM

// h global layout: per step, 8 chunks; each chunk = [64 rows x 272B hi][64 x 272B lo]
#define ROWB 272                      // 136 elems * 2B (row stride inside a chunk)
#define HALF_CHUNK 17408              // 64*272
#define CHUNK_BYTES 34816             // hi+lo
#define STEP_BYTES 278528             // 8*CHUNK_BYTES

// k_gru SMEM map (bytes)
#define W_HI_OFF 512
#define W_LO_OFF 50048                // 512 + 24*1032*2
#define A_OFF    99584                // 50048 + 49536
#define RED_OFF  204032               // 99584 + 3*34816
#define GRU_SMEM_BYTES 210176         // RED_OFF + 128*12*4

// ---------------- device scratch (no runtime allocation allowed) ------------
__device__ __align__(1024) unsigned char g_h[(size_t)(SS + 1) * STEP_BYTES];
__device__ __nv_bfloat16 g_Wg_hi[(size_t)NBLK * 24 * HH];     // gate weights hi [jb][c][k]
__device__ __nv_bfloat16 g_Wg_lo[(size_t)NBLK * 24 * HH];     // gate weights lo
__device__ float g_P[(size_t)VV * 3 * HH];                    // input preacts per token
__device__ __nv_bfloat16 g_WcT_hi[(size_t)OO * HH];           // (Wh@Wo)^T hi  [o][k]
__device__ __nv_bfloat16 g_WcT_lo[(size_t)OO * HH];           // (Wh@Wo)^T lo
__device__ float g_bc[OO];                                    // bh@Wo + bo
__device__ unsigned g_bar[SS];                                // per-step barrier counters

// byte offset of h(t, b, j) hi part; lo part = +HALF_CHUNK
__host__ __device__ __forceinline__ size_t haddr(int t, int b, int j) {
    return (size_t)t * STEP_BYTES + (size_t)(j >> 7) * CHUNK_BYTES +
           (size_t)b * ROWB + (size_t)(j & 127) * 2;
}

// ---------------- helpers ----------------------------------------------------
__device__ __forceinline__ uint32_t smem_u32(const void* p) {
    uint32_t a;
    asm("{ .reg .u64 t; cvta.to.shared.u64 t, %1; cvt.u32.u64 %0, t; }" : "=r"(a) : "l"(p));
    return a;
}
__device__ __forceinline__ void cp16(void* dst, const void* src) {
    unsigned d = (unsigned)__cvta_generic_to_shared(dst);
    asm volatile("cp.async.cg.shared.global [%0], [%1], 16;\n" ::"r"(d), "l"(src));
}
__device__ __forceinline__ void cp_commit() { asm volatile("cp.async.commit_group;\n"); }

__device__ __forceinline__ void mbar_init(uint32_t mbar, uint32_t cnt) {
    asm volatile("mbarrier.init.shared.b64 [%0], %1;" ::"r"(mbar), "r"(cnt) : "memory");
}
__device__ __forceinline__ void mbar_expect(uint32_t mbar, uint32_t bytes) {
    asm volatile("mbarrier.arrive.expect_tx.shared.b64 _, [%0], %1;"
                 ::"r"(mbar), "r"(bytes) : "memory");
}
__device__ __forceinline__ void mbar_wait(uint32_t mbar, int parity) {
    asm volatile(
        "{\n\t.reg .pred P1;\n\t"
        "W_%=:\n\t"
        "mbarrier.try_wait.parity.acquire.cta.shared::cta.b64 P1, [%0], %1, 0x989680;\n\t"
        "@P1 bra.uni D_%=;\n\t"
        "bra.uni W_%=;\n\t"
        "D_%=:\n\t}"
        ::"r"(mbar), "r"(parity) : "memory");
}
__device__ __forceinline__ void bulk_g2s(uint32_t dst, const void* src, uint32_t bytes,
                                         uint32_t mbar) {
    asm volatile(
        "cp.async.bulk.shared::cluster.global.mbarrier::complete_tx::bytes [%0], [%1], %2, [%3];"
        ::"r"(dst), "l"(src), "r"(bytes), "r"(mbar) : "memory");
}

__device__ __forceinline__ void ldsm4(uint32_t* r, uint32_t saddr) {
    asm volatile("ldmatrix.sync.aligned.m8n8.x4.shared.b16 {%0,%1,%2,%3}, [%4];\n"
                 : "=r"(r[0]), "=r"(r[1]), "=r"(r[2]), "=r"(r[3]) : "r"(saddr));
}
__device__ __forceinline__ void ldsm2(uint32_t* r, uint32_t saddr) {
    asm volatile("ldmatrix.sync.aligned.m8n8.x2.shared.b16 {%0,%1}, [%2];\n"
                 : "=r"(r[0]), "=r"(r[1]) : "r"(saddr));
}
__device__ __forceinline__ void mma_bf16(float* c, const uint32_t* a, const uint32_t* b) {
    asm volatile(
        "mma.sync.aligned.m16n8k16.row.col.f32.bf16.bf16.f32 "
        "{%0,%1,%2,%3},{%4,%5,%6,%7},{%8,%9},{%0,%1,%2,%3};\n"
        : "+f"(c[0]), "+f"(c[1]), "+f"(c[2]), "+f"(c[3])
        : "r"(a[0]), "r"(a[1]), "r"(a[2]), "r"(a[3]), "r"(b[0]), "r"(b[1]));
}
__device__ __forceinline__ float sigf(float x) { return 1.0f / (1.0f + expf(-x)); }

// ============================================================================
// init kernels
// ============================================================================
__global__ void k_zero_bar() {
    int i = blockIdx.x * blockDim.x + threadIdx.x;
    if (i < SS) g_bar[i] = 0u;
}

__global__ void k_pack_carry(const float* __restrict__ carry) {
    int i = blockIdx.x * blockDim.x + threadIdx.x;
    if (i >= BB * HH) return;
    int b = i >> 10, j = i & (HH - 1);
    float v = carry[i];
    __nv_bfloat16 hi = __float2bfloat16_rn(v);
    size_t ha = haddr(0, b, j);
    *(__nv_bfloat16*)(g_h + ha) = hi;
    *(__nv_bfloat16*)(g_h + ha + HALF_CHUNK) = __float2bfloat16_rn(v - __bfloat162float(hi));
}

__global__ void k_pack_w(const float* __restrict__ Whr, const float* __restrict__ Whz,
                         const float* __restrict__ Whn) {
    int idx = blockIdx.x * blockDim.x + threadIdx.x;
    if (idx >= NBLK * 24 * HH) return;
    int jb = idx / (24 * HH);
    int rem = idx - jb * (24 * HH);
    int c = rem >> 10;         // 0..23
    int k = rem & (HH - 1);
    int g = c >> 3;
    int j = (jb << 3) + (c & 7);
    const float* Wg = (g == 0) ? Whr : (g == 1) ? Whz : Whn;
    float v = Wg[(size_t)k * HH + j];
    __nv_bfloat16 hi = __float2bfloat16_rn(v);
    g_Wg_hi[idx] = hi;
    g_Wg_lo[idx] = __float2bfloat16_rn(v - __bfloat162float(hi));
}

__global__ void k_build_P(const float* __restrict__ emb,
                          const float* __restrict__ Wir, const float* __restrict__ bir,
                          const float* __restrict__ Wiz, const float* __restrict__ biz,
                          const float* __restrict__ Win, const float* __restrict__ bin_) {
    int idx = blockIdx.x * blockDim.x + threadIdx.x;
    if (idx >= VV * 3 * HH) return;
    int j = idx & (HH - 1);
    int g = (idx >> 10) % 3;
    int v = idx / (3 * HH);
    const float* W = (g == 0) ? Wir : (g == 1) ? Wiz : Win;
    const float* bb = (g == 0) ? bir : (g == 1) ? biz : bin_;
    float a = bb[j];
#pragma unroll 8
    for (int k = 0; k < EE; k++) a += emb[v * EE + k] * W[(size_t)k * HH + j];
    g_P[idx] = a;
}

__global__ void k_build_Wc(const float* __restrict__ Wh, const float* __restrict__ bh,
                           const float* __restrict__ Wo, const float* __restrict__ bo) {
    int idx = blockIdx.x * blockDim.x + threadIdx.x;
    if (idx >= HH * OO) return;
    int o = idx & (OO - 1);
    int k = idx >> 7;
    float a = 0.f;
#pragma unroll 8
    for (int j = 0; j < HH; j++) a += Wh[(size_t)k * HH + j] * Wo[(size_t)j * OO + o];
    __nv_bfloat16 hi = __float2bfloat16_rn(a);
    g_WcT_hi[(size_t)o * HH + k] = hi;
    g_WcT_lo[(size_t)o * HH + k] = __float2bfloat16_rn(a - __bfloat162float(hi));
    if (k == 0) {
        float c = bo[o];
#pragma unroll 8
        for (int j = 0; j < HH; j++) c += bh[j] * Wo[(size_t)j * OO + o];
        g_bc[o] = c;
    }
}

// ============================================================================
// persistent GRU kernel: 128 CTAs x 256 threads (2 warps/SMSP, K-interleaved),
// weights SMEM-resident, h streamed via cp.async.bulk 3-stage mbarrier ring.
// ============================================================================
__global__ void __launch_bounds__(256, 1)
k_gru(const int* __restrict__ inputs, const float* __restrict__ bhn) {
    extern __shared__ char smem[];
    const int tid = threadIdx.x;
    const int jb = blockIdx.x;
    const int wg = tid >> 7;           // warpgroup: 0 or 1 (K halves)
    const int w4 = (tid >> 5) & 3;     // SMSP / M-tile
    const int lane = tid & 31;
    const uint32_t sb = smem_u32(smem);
    const uint32_t mb0 = sb, mb1 = sb + 8, mb2 = sb + 16;
    int* stok = (int*)(smem + 32);
    float* sbhn = (float*)(smem + 288);
    __nv_bfloat16* whi = (__nv_bfloat16*)(smem + W_HI_OFF);
    __nv_bfloat16* wlo = (__nv_bfloat16*)(smem + W_LO_OFF);
    float* red = (float*)(smem + RED_OFF);

    if (tid == 0) { mbar_init(mb0, 1); mbar_init(mb1, 1); mbar_init(mb2, 1); }

    // one-time weight slice load (96KB)
    {
        const __nv_bfloat16* srcH = g_Wg_hi + (size_t)jb * 24 * HH;
        const __nv_bfloat16* srcL = g_Wg_lo + (size_t)jb * 24 * HH;
        for (int u = tid; u < 3072; u += 256) {
            int c = u >> 7, q = u & 127;
            cp16(whi + c * WP + q * 8, srcH + c * HH + q * 8);
            cp16(wlo + c * WP + q * 8, srcL + c * HH + q * 8);
        }
    }
    if (tid < 8) sbhn[tid] = bhn[jb * 8 + tid];
    cp_commit();
    asm volatile("cp.async.wait_group 0;\n" ::: "memory");
    __syncthreads();

    const uint32_t s_whi = sb + W_HI_OFF, s_wlo = sb + W_LO_OFF, sA = sb + A_OFF;
    const int a_row = (w4 << 4) + (lane & 15);
    const int a_k   = (lane >> 4) << 3;
    const int b_col = lane & 7;
    const int b_k   = ((lane >> 3) & 1) << 3;

    int ph0 = 0, ph1 = 0, ph2 = 0;

    for (int t = 0; t < SS; t++) {
        if (tid < 64) stok[tid] = inputs[tid * SS + t];
        const unsigned char* hbase = g_h + (size_t)t * STEP_BYTES;

        if (tid == 0) {
            mbar_expect(mb0, CHUNK_BYTES);
            bulk_g2s(sA, hbase, CHUNK_BYTES, mb0);
            mbar_expect(mb1, CHUNK_BYTES);
            bulk_g2s(sA + CHUNK_BYTES, hbase + CHUNK_BYTES, CHUNK_BYTES, mb1);
            mbar_expect(mb2, CHUNK_BYTES);
            bulk_g2s(sA + 2 * CHUNK_BYTES, hbase + 2 * (size_t)CHUNK_BYTES, CHUNK_BYTES, mb2);
        }

        // prefetch h_old for the epilogue (wg0 only) — hidden under the mainloop
        float hold[4];
        if (wg == 0) {
#pragma unroll
            for (int e = 0; e < 4; e++) {
                const int b = (w4 << 4) + (lane >> 2) + ((e >> 1) << 3);
                const int j = jb * 8 + ((lane & 3) << 1) + (e & 1);
                const size_t hao = haddr(t, b, j);
                hold[e] = __bfloat162float(*(const __nv_bfloat16*)(g_h + hao)) +
                          __bfloat162float(*(const __nv_bfloat16*)(g_h + hao + HALF_CHUNK));
            }
        }

        float accR[4] = {0.f, 0.f, 0.f, 0.f};
        float accZ[4] = {0.f, 0.f, 0.f, 0.f};
        float accN[4] = {0.f, 0.f, 0.f, 0.f};

#pragma unroll
        for (int kc = 0; kc < 8; kc++) {
            const int buf = kc % 3;
            const uint32_t mb = (buf == 0) ? mb0 : (buf == 1) ? mb1 : mb2;
            int* php = (buf == 0) ? &ph0 : (buf == 1) ? &ph1 : &ph2;
            mbar_wait(mb, *php);
            *php ^= 1;

            const uint32_t abh = sA + buf * CHUNK_BYTES + a_row * ROWB + a_k * 2;
#pragma unroll
            for (int ks2 = 0; ks2 < 4; ks2++) {
                const int ks = wg * 4 + ks2;      // K-interleave across warpgroups
                const int k0 = ks * 16;
                uint32_t ah[4], al[4];
                ldsm4(ah, abh + k0 * 2);
                ldsm4(al, abh + HALF_CHUNK + k0 * 2);
                uint32_t bhf[3][2], blf[3][2];
#pragma unroll
                for (int nt = 0; nt < 3; nt++) {
                    const uint32_t boff =
                        (uint32_t)((nt * 8 + b_col) * WP + kc * 128 + k0 + b_k) * 2;
                    ldsm2(bhf[nt], s_whi + boff);
                    ldsm2(blf[nt], s_wlo + boff);
                }
                // interleaved accumulators: same-acc RAW distance = 3
                mma_bf16(accR, ah, bhf[0]);
                mma_bf16(accZ, ah, bhf[1]);
                mma_bf16(accN, ah, bhf[2]);
                mma_bf16(accR, al, bhf[0]);
                mma_bf16(accZ, al, bhf[1]);
                mma_bf16(accN, al, bhf[2]);
                mma_bf16(accR, ah, blf[0]);
                mma_bf16(accZ, ah, blf[1]);
                mma_bf16(accN, ah, blf[2]);
            }
            __syncthreads();  // all 8 warps done reading buf
            if (kc < 5 && tid == 0) {
                mbar_expect(mb, CHUNK_BYTES);
                bulk_g2s(sA + buf * CHUNK_BYTES, hbase + (size_t)(kc + 3) * CHUNK_BYTES,
                         CHUNK_BYTES, mb);
            }
        }

        // --- cross-warpgroup reduction (wg1 -> wg0) ---
        if (wg == 1) {
            const int s = (tid & 127) * 12;
#pragma unroll
            for (int e = 0; e < 4; e++) {
                red[s + e] = accR[e];
                red[s + 4 + e] = accZ[e];
                red[s + 8 + e] = accN[e];
            }
        }
        __syncthreads();

        // --- epilogue: wg0 computes gates + h update for this block's 8 j-cols ---
        if (wg == 0) {
            const int s = tid * 12;
#pragma unroll
            for (int e = 0; e < 4; e++) {
                accR[e] += red[s + e];
                accZ[e] += red[s + 4 + e];
                accN[e] += red[s + 8 + e];
            }
#pragma unroll
            for (int e = 0; e < 4; e++) {
                const int b = (w4 << 4) + (lane >> 2) + ((e >> 1) << 3);
                const int col = ((lane & 3) << 1) + (e & 1);
                const int j = jb * 8 + col;
                const int tok = stok[b];
                const float* Pp = g_P + (size_t)tok * (3 * HH) + j;
                const float r = sigf(Pp[0] + accR[e]);
                const float z = sigf(Pp[HH] + accZ[e]);
                const float nv = tanhf(Pp[2 * HH] + r * (accN[e] + sbhn[col]));
                const float hn = nv + z * (hold[e] - nv);  // (1-z)*n + z*h
                const __nv_bfloat16 hi = __float2bfloat16_rn(hn);
                const size_t han = haddr(t + 1, b, j);
                *(__nv_bfloat16*)(g_h + han) = hi;
                *(__nv_bfloat16*)(g_h + han + HALF_CHUNK) =
                    __float2bfloat16_rn(hn - __bfloat162float(hi));
            }
        }

        // --- global step barrier (128 co-resident CTAs by construction) ---
        __threadfence();
        __syncthreads();
        if (tid == 0) {
            atomicAdd(&g_bar[t], 1u);
            while (((volatile unsigned*)g_bar)[t] < (unsigned)NBLK) { __nanosleep(64); }
            __threadfence();
        }
        __syncthreads();
    }
}

// ============================================================================
// carry output: reconstruct h[512] to fp32
// ============================================================================
__global__ void k_carry_out(float* __restrict__ out) {
    int i = blockIdx.x * blockDim.x + threadIdx.x;
    if (i >= BB * HH) return;
    int b = i >> 10, j = i & (HH - 1);
    size_t ha = haddr(SS, b, j);
    out[i] = __bfloat162float(*(const __nv_bfloat16*)(g_h + ha)) +
             __bfloat162float(*(const __nv_bfloat16*)(g_h + ha + HALF_CHUNK));
}

// ============================================================================
// logits GEMM: [32768,1024] @ WcT + bc, split-bf16 mma, m64 x n64 per block
// ============================================================================
__global__ void __launch_bounds__(128, 1) k_logits(float* __restrict__ out) {
    extern __shared__ char smem[];
    __nv_bfloat16* Ah = (__nv_bfloat16*)smem;      // 2*64*HP
    __nv_bfloat16* Al = Ah + 2 * 64 * HP;
    __nv_bfloat16* Bh = Al + 2 * 64 * HP;
    __nv_bfloat16* Bl = Bh + 2 * 64 * HP;

    const int tid = threadIdx.x;
    const int w = tid >> 5, lane = tid & 31;
    const int r0 = blockIdx.x * 64;            // global row block (row = b*512 + t)
    const int bidx = r0 >> 9;                  // batch
    const int t0 = r0 & (SS - 1);              // time offset
    const int o0 = blockIdx.y * 64;

    const __nv_bfloat16* srcBh = g_WcT_hi + (size_t)o0 * HH;
    const __nv_bfloat16* srcBl = g_WcT_lo + (size_t)o0 * HH;

    auto prefetch = [&](int kc, int buf) {
        for (int u = tid; u < 1024; u += 128) {
            int row = u >> 4, q = u & 15;
            const unsigned char* srcA = g_h + (size_t)(t0 + row + 1) * STEP_BYTES +
                                        (size_t)kc * CHUNK_BYTES + (size_t)bidx * ROWB +
                                        (size_t)q * 16;
            cp16(Ah + buf * (64 * HP) + row * HP + q * 8, srcA);
            cp16(Al + buf * (64 * HP) + row * HP + q * 8, srcA + HALF_CHUNK);
            cp16(Bh + buf * (64 * HP) + row * HP + q * 8,
                 srcBh + (size_t)row * HH + kc * 128 + q * 8);
            cp16(Bl + buf * (64 * HP) + row * HP + q * 8,
                 srcBl + (size_t)row * HH + kc * 128 + q * 8);
        }
        cp_commit();
    };

    const uint32_t sAh = (uint32_t)__cvta_generic_to_shared(Ah);
    const uint32_t sAl = (uint32_t)__cvta_generic_to_shared(Al);
    const uint32_t sBh = (uint32_t)__cvta_generic_to_shared(Bh);
    const uint32_t sBl = (uint32_t)__cvta_generic_to_shared(Bl);

    const int a_rl = lane & 15;
    const int a_k  = (lane >> 4) << 3;
    const int b_cl = lane & 7;
    const int b_k  = ((lane >> 3) & 1) << 3;

    float acc[4][2][4];
#pragma unroll
    for (int mt = 0; mt < 4; mt++)
#pragma unroll
        for (int nt = 0; nt < 2; nt++)
#pragma unroll
            for (int e = 0; e < 4; e++) acc[mt][nt][e] = 0.f;

    prefetch(0, 0);
    for (int kc = 0; kc < 8; kc++) {
        if (kc < 7) {
            prefetch(kc + 1, (kc + 1) & 1);
            asm volatile("cp.async.wait_group 1;\n");
        } else {
            asm volatile("cp.async.wait_group 0;\n");
        }
        __syncthreads();
        const int buf = kc & 1;
#pragma unroll
        for (int ks = 0; ks < 8; ks++) {
            const int k0 = ks * 16;
            uint32_t ah[4][4], al[4][4];
#pragma unroll
            for (int mt = 0; mt < 4; mt++) {
                const uint32_t ao =
                    (uint32_t)(buf * (64 * HP) + (mt * 16 + a_rl) * HP + k0 + a_k) * 2;
                ldsm4(ah[mt], sAh + ao);
                ldsm4(al[mt], sAl + ao);
            }
#pragma unroll
            for (int nt = 0; nt < 2; nt++) {
                const int colg = (w * 2 + nt) * 8 + b_cl;
                const uint32_t bo = (uint32_t)(buf * (64 * HP) + colg * HP + k0 + b_k) * 2;
                uint32_t bh2[2], bl2[2];
                ldsm2(bh2, sBh + bo);
                ldsm2(bl2, sBl + bo);
#pragma unroll
                for (int mt = 0; mt < 4; mt++) {
                    mma_bf16(acc[mt][nt], ah[mt], bh2);
                    mma_bf16(acc[mt][nt], al[mt], bh2);
                    mma_bf16(acc[mt][nt], ah[mt], bl2);
                }
            }
        }
        __syncthreads();
    }

#pragma unroll
    for (int mt = 0; mt < 4; mt++)
#pragma unroll
        for (int nt = 0; nt < 2; nt++)
#pragma unroll
            for (int e = 0; e < 4; e++) {
                const int row = r0 + mt * 16 + (lane >> 2) + ((e >> 1) << 3);
                const int o = o0 + (w * 2 + nt) * 8 + ((lane & 3) << 1) + (e & 1);
                out[(size_t)row * OO + o] = acc[mt][nt][e] + g_bc[o];
            }
}

// ============================================================================
// launcher
// ============================================================================
extern "C" void kernel_launch(void* const* d_in, const int* in_sizes, int n_in,
                              void* d_out, int out_size) {
    const int*   inputs = (const int*)d_in[0];
    const float* carry  = (const float*)d_in[1];
    const float* emb    = (const float*)d_in[2];
    const float* Wir    = (const float*)d_in[3];
    const float* bir    = (const float*)d_in[4];
    const float* Whr    = (const float*)d_in[5];
    const float* Wiz    = (const float*)d_in[6];
    const float* biz    = (const float*)d_in[7];
    const float* Whz    = (const float*)d_in[8];
    const float* Win    = (const float*)d_in[9];
    const float* bin_   = (const float*)d_in[10];
    const float* Whn    = (const float*)d_in[11];
    const float* bhn    = (const float*)d_in[12];
    const float* Wh     = (const float*)d_in[13];
    const float* bh     = (const float*)d_in[14];
    const float* Wo     = (const float*)d_in[15];
    const float* bo     = (const float*)d_in[16];

    float* out = (float*)d_out;

    const int LOG_SMEM = 4 * (2 * 64 * HP) * 2;  // 139264
    cudaFuncSetAttribute(k_gru, cudaFuncAttributeMaxDynamicSharedMemorySize, GRU_SMEM_BYTES);
    cudaFuncSetAttribute(k_logits, cudaFuncAttributeMaxDynamicSharedMemorySize, LOG_SMEM);

    k_zero_bar<<<2, 256>>>();
    k_pack_carry<<<(BB * HH + 255) / 256, 256>>>(carry);
    k_pack_w<<<(NBLK * 24 * HH + 255) / 256, 256>>>(Whr, Whz, Whn);
    k_build_P<<<(VV * 3 * HH + 255) / 256, 256>>>(emb, Wir, bir, Wiz, biz, Win, bin_);
    k_build_Wc<<<(HH * OO + 255) / 256, 256>>>(Wh, bh, Wo, bo);

    k_gru<<<NBLK, 256, GRU_SMEM_BYTES>>>(inputs, bhn);

    k_carry_out<<<(BB * HH + 255) / 256, 256>>>(out);

    dim3 lgrid(BB * SS / 64, OO / 64);  // (512, 2)
    k_logits<<<lgrid, 128, LOG_SMEM>>>(out + (size_t)BB * HH);
}

// round 11
// speedup vs baseline: 1.0747x; 1.0747x over previous
#include <cuda_runtime.h>
#include <cuda_fp16.h>
#include <cstdint>
#include <math.h>

// Problem constants
#define BB 64
#define SS 512
#define EE 128
#define HH 1024
#define VV 128
#define OO 128
#define NBLK 128          // GRU CTAs; each owns 8 j-columns (x3 gates = 24 weight rows)
#define HP 136            // padded row (elems) for logits kernel SMEM
#define WP 1032           // padded row (elems) for weight SMEM

// h global layout: per step, 8 chunks; each chunk = [64 rows x 272B hi][64 x 272B lo]
#define ROWB 272                      // 136 elems * 2B (row stride inside a chunk)
#define HALF_CHUNK 17408              // 64*272 (hi part; also the lo offset)
#define CHUNK_BYTES 34816             // hi+lo
#define STEP_BYTES 278528             // 8*CHUNK_BYTES

// k_gru SMEM map (bytes): mainloop streams ONLY the hi half of each chunk
#define W_HI_OFF 512
#define W_LO_OFF 50048                // 512 + 24*1032*2
#define A_OFF    99584                // 50048 + 49536
#define GRU_SMEM_BYTES 151808         // 99584 + 3*17408  (>114KB -> 1 CTA/SM)

// ---------------- device scratch (no runtime allocation allowed) ------------
__device__ __align__(1024) unsigned char g_h[(size_t)(SS + 1) * STEP_BYTES];
__device__ __half g_Wg_hi[(size_t)NBLK * 24 * HH];            // gate weights hi [jb][c][k]
__device__ __half g_Wg_lo[(size_t)NBLK * 24 * HH];            // gate weights lo
__device__ float g_P[(size_t)VV * 3 * HH];                    // input preacts per token
__device__ __half g_WcT_hi[(size_t)OO * HH];                  // (Wh@Wo)^T hi  [o][k]
__device__ __half g_WcT_lo[(size_t)OO * HH];                  // (Wh@Wo)^T lo
__device__ float g_bc[OO];                                    // bh@Wo + bo
__device__ unsigned g_bar[(SS + 1) * 8];                      // per-(step,chunk) counters

// byte offset of h(t, b, j) hi part; lo part = +HALF_CHUNK
__host__ __device__ __forceinline__ size_t haddr(int t, int b, int j) {
    return (size_t)t * STEP_BYTES + (size_t)(j >> 7) * CHUNK_BYTES +
           (size_t)b * ROWB + (size_t)(j & 127) * 2;
}

// ---------------- helpers ----------------------------------------------------
__device__ __forceinline__ uint32_t smem_u32(const void* p) {
    uint32_t a;
    asm("{ .reg .u64 t; cvta.to.shared.u64 t, %1; cvt.u32.u64 %0, t; }" : "=r"(a) : "l"(p));
    return a;
}
__device__ __forceinline__ void cp16(void* dst, const void* src) {
    unsigned d = (unsigned)__cvta_generic_to_shared(dst);
    asm volatile("cp.async.cg.shared.global [%0], [%1], 16;\n" ::"r"(d), "l"(src));
}
__device__ __forceinline__ void cp_commit() { asm volatile("cp.async.commit_group;\n"); }

__device__ __forceinline__ void mbar_init(uint32_t mbar, uint32_t cnt) {
    asm volatile("mbarrier.init.shared.b64 [%0], %1;" ::"r"(mbar), "r"(cnt) : "memory");
}
__device__ __forceinline__ void mbar_expect(uint32_t mbar, uint32_t bytes) {
    asm volatile("mbarrier.arrive.expect_tx.shared.b64 _, [%0], %1;"
                 ::"r"(mbar), "r"(bytes) : "memory");
}
__device__ __forceinline__ void mbar_wait(uint32_t mbar, int parity) {
    asm volatile(
        "{\n\t.reg .pred P1;\n\t"
        "W_%=:\n\t"
        "mbarrier.try_wait.parity.acquire.cta.shared::cta.b64 P1, [%0], %1, 0x989680;\n\t"
        "@P1 bra.uni D_%=;\n\t"
        "bra.uni W_%=;\n\t"
        "D_%=:\n\t}"
        ::"r"(mbar), "r"(parity) : "memory");
}
__device__ __forceinline__ void bulk_g2s(uint32_t dst, const void* src, uint32_t bytes,
                                         uint32_t mbar) {
    asm volatile(
        "cp.async.bulk.shared::cluster.global.mbarrier::complete_tx::bytes [%0], [%1], %2, [%3];"
        ::"r"(dst), "l"(src), "r"(bytes), "r"(mbar) : "memory");
}
// wait until producer counter reaches 16 (gpu-scope acquire)
__device__ __forceinline__ void wait16(const unsigned* addr) {
    unsigned v;
    while (true) {
        asm volatile("ld.acquire.gpu.global.u32 %0, [%1];" : "=r"(v) : "l"(addr) : "memory");
        if (v >= 16u) break;
        __nanosleep(32);
    }
}

__device__ __forceinline__ void ldsm4(uint32_t* r, uint32_t saddr) {
    asm volatile("ldmatrix.sync.aligned.m8n8.x4.shared.b16 {%0,%1,%2,%3}, [%4];\n"
                 : "=r"(r[0]), "=r"(r[1]), "=r"(r[2]), "=r"(r[3]) : "r"(saddr));
}
__device__ __forceinline__ void ldsm2(uint32_t* r, uint32_t saddr) {
    asm volatile("ldmatrix.sync.aligned.m8n8.x2.shared.b16 {%0,%1}, [%2];\n"
                 : "=r"(r[0]), "=r"(r[1]) : "r"(saddr));
}
__device__ __forceinline__ void mma_f16(float* c, const uint32_t* a, const uint32_t* b) {
    asm volatile(
        "mma.sync.aligned.m16n8k16.row.col.f32.f16.f16.f32 "
        "{%0,%1,%2,%3},{%4,%5,%6,%7},{%8,%9},{%0,%1,%2,%3};\n"
        : "+f"(c[0]), "+f"(c[1]), "+f"(c[2]), "+f"(c[3])
        : "r"(a[0]), "r"(a[1]), "r"(a[2]), "r"(a[3]), "r"(b[0]), "r"(b[1]));
}
__device__ __forceinline__ float sigf(float x) { return 1.0f / (1.0f + expf(-x)); }

// ============================================================================
// init kernels
// ============================================================================
__global__ void k_zero_bar() {
    int i = blockIdx.x * blockDim.x + threadIdx.x;
    if (i < (SS + 1) * 8) g_bar[i] = 0u;
}

__global__ void k_pack_carry(const float* __restrict__ carry) {
    int i = blockIdx.x * blockDim.x + threadIdx.x;
    if (i >= BB * HH) return;
    int b = i >> 10, j = i & (HH - 1);
    float v = carry[i];
    __half hi = __float2half_rn(v);
    size_t ha = haddr(0, b, j);
    *(__half*)(g_h + ha) = hi;
    *(__half*)(g_h + ha + HALF_CHUNK) = __float2half_rn(v - __half2float(hi));
}

__global__ void k_pack_w(const float* __restrict__ Whr, const float* __restrict__ Whz,
                         const float* __restrict__ Whn) {
    int idx = blockIdx.x * blockDim.x + threadIdx.x;
    if (idx >= NBLK * 24 * HH) return;
    int jb = idx / (24 * HH);
    int rem = idx - jb * (24 * HH);
    int c = rem >> 10;         // 0..23
    int k = rem & (HH - 1);
    int g = c >> 3;
    int j = (jb << 3) + (c & 7);
    const float* Wg = (g == 0) ? Whr : (g == 1) ? Whz : Whn;
    float v = Wg[(size_t)k * HH + j];
    __half hi = __float2half_rn(v);
    g_Wg_hi[idx] = hi;
    g_Wg_lo[idx] = __float2half_rn(v - __half2float(hi));
}

__global__ void k_build_P(const float* __restrict__ emb,
                          const float* __restrict__ Wir, const float* __restrict__ bir,
                          const float* __restrict__ Wiz, const float* __restrict__ biz,
                          const float* __restrict__ Win, const float* __restrict__ bin_) {
    int idx = blockIdx.x * blockDim.x + threadIdx.x;
    if (idx >= VV * 3 * HH) return;
    int j = idx & (HH - 1);
    int g = (idx >> 10) % 3;
    int v = idx / (3 * HH);
    const float* W = (g == 0) ? Wir : (g == 1) ? Wiz : Win;
    const float* bb = (g == 0) ? bir : (g == 1) ? biz : bin_;
    float a = bb[j];
#pragma unroll 8
    for (int k = 0; k < EE; k++) a += emb[v * EE + k] * W[(size_t)k * HH + j];
    g_P[idx] = a;
}

__global__ void k_build_Wc(const float* __restrict__ Wh, const float* __restrict__ bh,
                           const float* __restrict__ Wo, const float* __restrict__ bo) {
    int idx = blockIdx.x * blockDim.x + threadIdx.x;
    if (idx >= HH * OO) return;
    int o = idx & (OO - 1);
    int k = idx >> 7;
    float a = 0.f;
#pragma unroll 8
    for (int j = 0; j < HH; j++) a += Wh[(size_t)k * HH + j] * Wo[(size_t)j * OO + o];
    __half hi = __float2half_rn(a);
    g_WcT_hi[(size_t)o * HH + k] = hi;
    g_WcT_lo[(size_t)o * HH + k] = __float2half_rn(a - __half2float(hi));
    if (k == 0) {
        float c = bo[o];
#pragma unroll 8
        for (int j = 0; j < HH; j++) c += bh[j] * Wo[(size_t)j * OO + o];
        g_bc[o] = c;
    }
}

// ============================================================================
// persistent GRU kernel: 128 CTAs x 128 threads.
// fp16 2-term split (W = hi+lo fp16; h fed as single fp16, stored hi/lo).
// Per-chunk producer counters replace the full-chip barrier.
// ============================================================================
__global__ void __launch_bounds__(128, 1)
k_gru(const int* __restrict__ inputs, const float* __restrict__ bhn) {
    extern __shared__ char smem[];
    const int tid = threadIdx.x;
    const int jb = blockIdx.x;
    const int w = tid >> 5, lane = tid & 31;
    const uint32_t sb = smem_u32(smem);
    const uint32_t mb0 = sb, mb1 = sb + 8, mb2 = sb + 16;
    int* stok = (int*)(smem + 32);
    float* sbhn = (float*)(smem + 288);
    __half* whi = (__half*)(smem + W_HI_OFF);
    __half* wlo = (__half*)(smem + W_LO_OFF);

    if (tid == 0) { mbar_init(mb0, 1); mbar_init(mb1, 1); mbar_init(mb2, 1); }

    // one-time weight slice load (96KB)
    {
        const __half* srcH = g_Wg_hi + (size_t)jb * 24 * HH;
        const __half* srcL = g_Wg_lo + (size_t)jb * 24 * HH;
        for (int u = tid; u < 3072; u += 128) {
            int c = u >> 7, q = u & 127;
            cp16(whi + c * WP + q * 8, srcH + c * HH + q * 8);
            cp16(wlo + c * WP + q * 8, srcL + c * HH + q * 8);
        }
    }
    if (tid < 8) sbhn[tid] = bhn[jb * 8 + tid];
    cp_commit();
    asm volatile("cp.async.wait_group 0;\n" ::: "memory");
    __syncthreads();

    const uint32_t s_whi = sb + W_HI_OFF, s_wlo = sb + W_LO_OFF, sA = sb + A_OFF;
    const int a_row = (w << 4) + (lane & 15);
    const int a_k   = (lane >> 4) << 3;
    const int b_col = lane & 7;
    const int b_k   = ((lane >> 3) & 1) << 3;
    const int cb    = jb >> 4;          // chunk this CTA produces into

    int ph0 = 0, ph1 = 0, ph2 = 0;

    for (int t = 0; t < SS; t++) {
        if (tid < 64) stok[tid] = inputs[tid * SS + t];
        const unsigned char* hbase = g_h + (size_t)t * STEP_BYTES;

        if (tid == 0) {
            // poll producers of chunks 0..2, then issue hi-half bulk loads
#pragma unroll
            for (int c = 0; c < 3; c++) {
                if (t > 0) wait16(&g_bar[t * 8 + c]);
                const uint32_t mb = (c == 0) ? mb0 : (c == 1) ? mb1 : mb2;
                mbar_expect(mb, HALF_CHUNK);
                bulk_g2s(sA + c * HALF_CHUNK, hbase + (size_t)c * CHUNK_BYTES,
                         HALF_CHUNK, mb);
            }
        }

        // prefetch h_old (own columns; written by this CTA last step)
        float hold[4];
#pragma unroll
        for (int e = 0; e < 4; e++) {
            const int b = (w << 4) + (lane >> 2) + ((e >> 1) << 3);
            const int j = jb * 8 + ((lane & 3) << 1) + (e & 1);
            const size_t hao = haddr(t, b, j);
            hold[e] = __half2float(*(const __half*)(g_h + hao)) +
                      __half2float(*(const __half*)(g_h + hao + HALF_CHUNK));
        }

        float accR[4] = {0.f, 0.f, 0.f, 0.f};
        float accZ[4] = {0.f, 0.f, 0.f, 0.f};
        float accN[4] = {0.f, 0.f, 0.f, 0.f};

#pragma unroll
        for (int kc = 0; kc < 8; kc++) {
            const int buf = kc % 3;
            const uint32_t mb = (buf == 0) ? mb0 : (buf == 1) ? mb1 : mb2;
            int* php = (buf == 0) ? &ph0 : (buf == 1) ? &ph1 : &ph2;
            mbar_wait(mb, *php);
            *php ^= 1;

            const uint32_t abh = sA + buf * HALF_CHUNK + a_row * ROWB + a_k * 2;
#pragma unroll
            for (int ks = 0; ks < 8; ks++) {
                const int k0 = ks * 16;
                uint32_t a[4];
                ldsm4(a, abh + k0 * 2);
                uint32_t bhf[3][2], blf[3][2];
#pragma unroll
                for (int nt = 0; nt < 3; nt++) {
                    const uint32_t boff =
                        (uint32_t)((nt * 8 + b_col) * WP + kc * 128 + k0 + b_k) * 2;
                    ldsm2(bhf[nt], s_whi + boff);
                    ldsm2(blf[nt], s_wlo + boff);
                }
                // interleaved: same-acc RAW distance = 3
                mma_f16(accR, a, bhf[0]);
                mma_f16(accZ, a, bhf[1]);
                mma_f16(accN, a, bhf[2]);
                mma_f16(accR, a, blf[0]);
                mma_f16(accZ, a, blf[1]);
                mma_f16(accN, a, blf[2]);
            }
            __syncthreads();  // all warps done reading buf
            if (kc < 5 && tid == 0) {
                if (t > 0) wait16(&g_bar[t * 8 + kc + 3]);
                mbar_expect(mb, HALF_CHUNK);
                bulk_g2s(sA + buf * HALF_CHUNK, hbase + (size_t)(kc + 3) * CHUNK_BYTES,
                         HALF_CHUNK, mb);
            }
        }

        // --- epilogue: gates + h update for this block's 8 j-columns ---
#pragma unroll
        for (int e = 0; e < 4; e++) {
            const int b = (w << 4) + (lane >> 2) + ((e >> 1) << 3);
            const int col = ((lane & 3) << 1) + (e & 1);
            const int j = jb * 8 + col;
            const int tok = stok[b];
            const float* Pp = g_P + (size_t)tok * (3 * HH) + j;
            const float r = sigf(Pp[0] + accR[e]);
            const float z = sigf(Pp[HH] + accZ[e]);
            const float nv = tanhf(Pp[2 * HH] + r * (accN[e] + sbhn[col]));
            const float hn = nv + z * (hold[e] - nv);  // (1-z)*n + z*h
            const __half hi = __float2half_rn(hn);
            const size_t han = haddr(t + 1, b, j);
            *(__half*)(g_h + han) = hi;
            *(__half*)(g_h + han + HALF_CHUNK) = __float2half_rn(hn - __half2float(hi));
        }

        // --- signal: this CTA's contribution to h_{t+1} chunk cb is done ---
        __threadfence();
        __syncthreads();
        if (tid == 0) {
            asm volatile("red.release.gpu.global.add.u32 [%0], %1;"
                         ::"l"(&g_bar[(t + 1) * 8 + cb]), "r"(1u) : "memory");
        }
    }
}

// ============================================================================
// carry output: reconstruct h[512] to fp32
// ============================================================================
__global__ void k_carry_out(float* __restrict__ out) {
    int i = blockIdx.x * blockDim.x + threadIdx.x;
    if (i >= BB * HH) return;
    int b = i >> 10, j = i & (HH - 1);
    size_t ha = haddr(SS, b, j);
    out[i] = __half2float(*(const __half*)(g_h + ha)) +
             __half2float(*(const __half*)(g_h + ha + HALF_CHUNK));
}

// ============================================================================
// logits GEMM: [32768,1024] @ WcT + bc, split-fp16 mma, m64 x n64 per block
// ============================================================================
__global__ void __launch_bounds__(128, 1) k_logits(float* __restrict__ out) {
    extern __shared__ char smem[];
    __half* Ah = (__half*)smem;        // 2*64*HP
    __half* Al = Ah + 2 * 64 * HP;
    __half* Bh = Al + 2 * 64 * HP;
    __half* Bl = Bh + 2 * 64 * HP;

    const int tid = threadIdx.x;
    const int w = tid >> 5, lane = tid & 31;
    const int r0 = blockIdx.x * 64;            // global row block (row = b*512 + t)
    const int bidx = r0 >> 9;                  // batch
    const int t0 = r0 & (SS - 1);              // time offset
    const int o0 = blockIdx.y * 64;

    const __half* srcBh = g_WcT_hi + (size_t)o0 * HH;
    const __half* srcBl = g_WcT_lo + (size_t)o0 * HH;

    auto prefetch = [&](int kc, int buf) {
        for (int u = tid; u < 1024; u += 128) {
            int row = u >> 4, q = u & 15;
            const unsigned char* srcA = g_h + (size_t)(t0 + row + 1) * STEP_BYTES +
                                        (size_t)kc * CHUNK_BYTES + (size_t)bidx * ROWB +
                                        (size_t)q * 16;
            cp16(Ah + buf * (64 * HP) + row * HP + q * 8, srcA);
            cp16(Al + buf * (64 * HP) + row * HP + q * 8, srcA + HALF_CHUNK);
            cp16(Bh + buf * (64 * HP) + row * HP + q * 8,
                 srcBh + (size_t)row * HH + kc * 128 + q * 8);
            cp16(Bl + buf * (64 * HP) + row * HP + q * 8,
                 srcBl + (size_t)row * HH + kc * 128 + q * 8);
        }
        cp_commit();
    };

    const uint32_t sAh = (uint32_t)__cvta_generic_to_shared(Ah);
    const uint32_t sAl = (uint32_t)__cvta_generic_to_shared(Al);
    const uint32_t sBh = (uint32_t)__cvta_generic_to_shared(Bh);
    const uint32_t sBl = (uint32_t)__cvta_generic_to_shared(Bl);

    const int a_rl = lane & 15;
    const int a_k  = (lane >> 4) << 3;
    const int b_cl = lane & 7;
    const int b_k  = ((lane >> 3) & 1) << 3;

    float acc[4][2][4];
#pragma unroll
    for (int mt = 0; mt < 4; mt++)
#pragma unroll
        for (int nt = 0; nt < 2; nt++)
#pragma unroll
            for (int e = 0; e < 4; e++) acc[mt][nt][e] = 0.f;

    prefetch(0, 0);
    for (int kc = 0; kc < 8; kc++) {
        if (kc < 7) {
            prefetch(kc + 1, (kc + 1) & 1);
            asm volatile("cp.async.wait_group 1;\n");
        } else {
            asm volatile("cp.async.wait_group 0;\n");
        }
        __syncthreads();
        const int buf = kc & 1;
#pragma unroll
        for (int ks = 0; ks < 8; ks++) {
            const int k0 = ks * 16;
            uint32_t ah[4][4], al[4][4];
#pragma unroll
            for (int mt = 0; mt < 4; mt++) {
                const uint32_t ao =
                    (uint32_t)(buf * (64 * HP) + (mt * 16 + a_rl) * HP + k0 + a_k) * 2;
                ldsm4(ah[mt], sAh + ao);
                ldsm4(al[mt], sAl + ao);
            }
#pragma unroll
            for (int nt = 0; nt < 2; nt++) {
                const int colg = (w * 2 + nt) * 8 + b_cl;
                const uint32_t bo = (uint32_t)(buf * (64 * HP) + colg * HP + k0 + b_k) * 2;
                uint32_t bh2[2], bl2[2];
                ldsm2(bh2, sBh + bo);
                ldsm2(bl2, sBl + bo);
#pragma unroll
                for (int mt = 0; mt < 4; mt++) {
                    mma_f16(acc[mt][nt], ah[mt], bh2);
                    mma_f16(acc[mt][nt], al[mt], bh2);
                    mma_f16(acc[mt][nt], ah[mt], bl2);
                }
            }
        }
        __syncthreads();
    }

#pragma unroll
    for (int mt = 0; mt < 4; mt++)
#pragma unroll
        for (int nt = 0; nt < 2; nt++)
#pragma unroll
            for (int e = 0; e < 4; e++) {
                const int row = r0 + mt * 16 + (lane >> 2) + ((e >> 1) << 3);
                const int o = o0 + (w * 2 + nt) * 8 + ((lane & 3) << 1) + (e & 1);
                out[(size_t)row * OO + o] = acc[mt][nt][e] + g_bc[o];
            }
}

// ============================================================================
// launcher
// ============================================================================
extern "C" void kernel_launch(void* const* d_in, const int* in_sizes, int n_in,
                              void* d_out, int out_size) {
    const int*   inputs = (const int*)d_in[0];
    const float* carry  = (const float*)d_in[1];
    const float* emb    = (const float*)d_in[2];
    const float* Wir    = (const float*)d_in[3];
    const float* bir    = (const float*)d_in[4];
    const float* Whr    = (const float*)d_in[5];
    const float* Wiz    = (const float*)d_in[6];
    const float* biz    = (const float*)d_in[7];
    const float* Whz    = (const float*)d_in[8];
    const float* Win    = (const float*)d_in[9];
    const float* bin_   = (const float*)d_in[10];
    const float* Whn    = (const float*)d_in[11];
    const float* bhn    = (const float*)d_in[12];
    const float* Wh     = (const float*)d_in[13];
    const float* bh     = (const float*)d_in[14];
    const float* Wo     = (const float*)d_in[15];
    const float* bo     = (const float*)d_in[16];

    float* out = (float*)d_out;

    const int LOG_SMEM = 4 * (2 * 64 * HP) * 2;  // 139264
    cudaFuncSetAttribute(k_gru, cudaFuncAttributeMaxDynamicSharedMemorySize, GRU_SMEM_BYTES);
    cudaFuncSetAttribute(k_logits, cudaFuncAttributeMaxDynamicSharedMemorySize, LOG_SMEM);

    k_zero_bar<<<17, 256>>>();
    k_pack_carry<<<(BB * HH + 255) / 256, 256>>>(carry);
    k_pack_w<<<(NBLK * 24 * HH + 255) / 256, 256>>>(Whr, Whz, Whn);
    k_build_P<<<(VV * 3 * HH + 255) / 256, 256>>>(emb, Wir, bir, Wiz, biz, Win, bin_);
    k_build_Wc<<<(HH * OO + 255) / 256, 256>>>(Wh, bh, Wo, bo);

    k_gru<<<NBLK, 128, GRU_SMEM_BYTES>>>(inputs, bhn);

    k_carry_out<<<(BB * HH + 255) / 256, 256>>>(out);

    dim3 lgrid(BB * SS / 64, OO / 64);  // (512, 2)
    k_logits<<<lgrid, 128, LOG_SMEM>>>(out + (size_t)BB * HH);
}

// round 13
// speedup vs baseline: 1.4550x; 1.3538x over previous
#include <cuda_runtime.h>
#include <cuda_fp16.h>
#include <cstdint>
#include <math.h>

// Problem constants
#define BB 64
#define SS 512
#define EE 128
#define HH 1024
#define VV 128
#define OO 128
#define NBLK 128          // GRU CTAs; each owns 8 j-columns (x3 gates = 24 weight rows)
#define HP 136            // padded row (elems) for logits kernel SMEM
#define WP 1032           // padded row (elems) for weight SMEM

// h global layout: per step, 8 chunks; each chunk = [64 rows x 272B hi][64 x 272B lo]
#define ROWB 272                      // 136 elems * 2B (row stride inside a chunk)
#define HALF_CHUNK 17408              // 64*272 (hi part; also the lo offset)
#define CHUNK_BYTES 34816             // hi+lo
#define STEP_BYTES 278528             // 8*CHUNK_BYTES
#define MEGA_BYTES 34816              // SMEM megachunk: 2 hi-halves

// k_gru SMEM map (bytes): mainloop streams ONLY hi halves, 256 k per megachunk
#define W_HI_OFF 512
#define W_LO_OFF 50048                // 512 + 24*1032*2
#define A_OFF    99584                // 50048 + 49536
#define GRU_SMEM_BYTES 204032         // 99584 + 3*34816 (>114KB -> 1 CTA/SM)

// ---------------- device scratch (no runtime allocation allowed) ------------
__device__ __align__(1024) unsigned char g_h[(size_t)(SS + 1) * STEP_BYTES];
__device__ __half g_Wg_hi[(size_t)NBLK * 24 * HH];            // gate weights hi [jb][c][k]
__device__ __half g_Wg_lo[(size_t)NBLK * 24 * HH];            // gate weights lo
__device__ float g_P[(size_t)VV * 3 * HH];                    // input preacts per token
__device__ __half g_WcT_hi[(size_t)OO * HH];                  // (Wh@Wo)^T hi  [o][k]
__device__ __half g_WcT_lo[(size_t)OO * HH];                  // (Wh@Wo)^T lo
__device__ float g_bc[OO];                                    // bh@Wo + bo
__device__ unsigned g_bar[(SS + 1) * 4];                      // per-(step,megachunk) counters

// byte offset of h(t, b, j) hi part; lo part = +HALF_CHUNK
__host__ __device__ __forceinline__ size_t haddr(int t, int b, int j) {
    return (size_t)t * STEP_BYTES + (size_t)(j >> 7) * CHUNK_BYTES +
           (size_t)b * ROWB + (size_t)(j & 127) * 2;
}

// ---------------- helpers ----------------------------------------------------
__device__ __forceinline__ uint32_t smem_u32(const void* p) {
    uint32_t a;
    asm("{ .reg .u64 t; cvta.to.shared.u64 t, %1; cvt.u32.u64 %0, t; }" : "=r"(a) : "l"(p));
    return a;
}
__device__ __forceinline__ void cp16(void* dst, const void* src) {
    unsigned d = (unsigned)__cvta_generic_to_shared(dst);
    asm volatile("cp.async.cg.shared.global [%0], [%1], 16;\n" ::"r"(d), "l"(src));
}
__device__ __forceinline__ void cp_commit() { asm volatile("cp.async.commit_group;\n"); }

__device__ __forceinline__ void mbar_init(uint32_t mbar, uint32_t cnt) {
    asm volatile("mbarrier.init.shared.b64 [%0], %1;" ::"r"(mbar), "r"(cnt) : "memory");
}
__device__ __forceinline__ void mbar_expect(uint32_t mbar, uint32_t bytes) {
    asm volatile("mbarrier.arrive.expect_tx.shared.b64 _, [%0], %1;"
                 ::"r"(mbar), "r"(bytes) : "memory");
}
__device__ __forceinline__ void mbar_wait(uint32_t mbar, int parity) {
    asm volatile(
        "{\n\t.reg .pred P1;\n\t"
        "W_%=:\n\t"
        "mbarrier.try_wait.parity.acquire.cta.shared::cta.b64 P1, [%0], %1, 0x989680;\n\t"
        "@P1 bra.uni D_%=;\n\t"
        "bra.uni W_%=;\n\t"
        "D_%=:\n\t}"
        ::"r"(mbar), "r"(parity) : "memory");
}
__device__ __forceinline__ void bulk_g2s(uint32_t dst, const void* src, uint32_t bytes,
                                         uint32_t mbar) {
    asm volatile(
        "cp.async.bulk.shared::cluster.global.mbarrier::complete_tx::bytes [%0], [%1], %2, [%3];"
        ::"r"(dst), "l"(src), "r"(bytes), "r"(mbar) : "memory");
}
// wait until producer counter reaches 32 (gpu-scope acquire)
__device__ __forceinline__ void wait32(const unsigned* addr) {
    unsigned v;
    while (true) {
        asm volatile("ld.acquire.gpu.global.u32 %0, [%1];" : "=r"(v) : "l"(addr) : "memory");
        if (v >= 32u) break;
        __nanosleep(32);
    }
}

__device__ __forceinline__ void ldsm4(uint32_t* r, uint32_t saddr) {
    asm volatile("ldmatrix.sync.aligned.m8n8.x4.shared.b16 {%0,%1,%2,%3}, [%4];\n"
                 : "=r"(r[0]), "=r"(r[1]), "=r"(r[2]), "=r"(r[3]) : "r"(saddr));
}
__device__ __forceinline__ void ldsm2(uint32_t* r, uint32_t saddr) {
    asm volatile("ldmatrix.sync.aligned.m8n8.x2.shared.b16 {%0,%1}, [%2];\n"
                 : "=r"(r[0]), "=r"(r[1]) : "r"(saddr));
}
__device__ __forceinline__ void mma_f16(float* c, const uint32_t* a, const uint32_t* b) {
    asm volatile(
        "mma.sync.aligned.m16n8k16.row.col.f32.f16.f16.f32 "
        "{%0,%1,%2,%3},{%4,%5,%6,%7},{%8,%9},{%0,%1,%2,%3};\n"
        : "+f"(c[0]), "+f"(c[1]), "+f"(c[2]), "+f"(c[3])
        : "r"(a[0]), "r"(a[1]), "r"(a[2]), "r"(a[3]), "r"(b[0]), "r"(b[1]));
}
__device__ __forceinline__ float sigf(float x) { return 1.0f / (1.0f + expf(-x)); }

// ============================================================================
// init kernels (fused so k_gru is the 4th launch -> lands in ncu's window)
// ============================================================================
__global__ void k_init0(const float* __restrict__ carry) {
    int i = blockIdx.x * blockDim.x + threadIdx.x;
    if (i < BB * HH) {
        int b = i >> 10, j = i & (HH - 1);
        float v = carry[i];
        __half hi = __float2half_rn(v);
        size_t ha = haddr(0, b, j);
        *(__half*)(g_h + ha) = hi;
        *(__half*)(g_h + ha + HALF_CHUNK) = __float2half_rn(v - __half2float(hi));
    } else {
        int q = i - BB * HH;
        if (q < (SS + 1) * 4) g_bar[q] = 0u;
    }
}

__global__ void k_pack_w(const float* __restrict__ Whr, const float* __restrict__ Whz,
                         const float* __restrict__ Whn) {
    int idx = blockIdx.x * blockDim.x + threadIdx.x;
    if (idx >= NBLK * 24 * HH) return;
    int jb = idx / (24 * HH);
    int rem = idx - jb * (24 * HH);
    int c = rem >> 10;         // 0..23
    int k = rem & (HH - 1);
    int g = c >> 3;
    int j = (jb << 3) + (c & 7);
    const float* Wg = (g == 0) ? Whr : (g == 1) ? Whz : Whn;
    float v = Wg[(size_t)k * HH + j];
    __half hi = __float2half_rn(v);
    g_Wg_hi[idx] = hi;
    g_Wg_lo[idx] = __float2half_rn(v - __half2float(hi));
}

__global__ void k_build_P(const float* __restrict__ emb,
                          const float* __restrict__ Wir, const float* __restrict__ bir,
                          const float* __restrict__ Wiz, const float* __restrict__ biz,
                          const float* __restrict__ Win, const float* __restrict__ bin_) {
    int idx = blockIdx.x * blockDim.x + threadIdx.x;
    if (idx >= VV * 3 * HH) return;
    int j = idx & (HH - 1);
    int g = (idx >> 10) % 3;
    int v = idx / (3 * HH);
    const float* W = (g == 0) ? Wir : (g == 1) ? Wiz : Win;
    const float* bb = (g == 0) ? bir : (g == 1) ? biz : bin_;
    float a = bb[j];
#pragma unroll 8
    for (int k = 0; k < EE; k++) a += emb[v * EE + k] * W[(size_t)k * HH + j];
    g_P[idx] = a;
}

__global__ void k_build_Wc(const float* __restrict__ Wh, const float* __restrict__ bh,
                           const float* __restrict__ Wo, const float* __restrict__ bo) {
    int idx = blockIdx.x * blockDim.x + threadIdx.x;
    if (idx >= HH * OO) return;
    int o = idx & (OO - 1);
    int k = idx >> 7;
    float a = 0.f;
#pragma unroll 8
    for (int j = 0; j < HH; j++) a += Wh[(size_t)k * HH + j] * Wo[(size_t)j * OO + o];
    __half hi = __float2half_rn(a);
    g_WcT_hi[(size_t)o * HH + k] = hi;
    g_WcT_lo[(size_t)o * HH + k] = __float2half_rn(a - __half2float(hi));
    if (k == 0) {
        float c = bo[o];
#pragma unroll 8
        for (int j = 0; j < HH; j++) c += bh[j] * Wo[(size_t)j * OO + o];
        g_bc[o] = c;
    }
}

// ============================================================================
// persistent GRU kernel: 128 CTAs x 128 threads, fp16 2-term split.
// 4 megachunks/step (256 k each), packed hi+lo B ldsm4, hoisted epilogue loads.
// ============================================================================
__global__ void __launch_bounds__(128, 1)
k_gru(const int* __restrict__ inputs, const float* __restrict__ bhn) {
    extern __shared__ char smem[];
    const int tid = threadIdx.x;
    const int jb = blockIdx.x;
    const int w = tid >> 5, lane = tid & 31;
    const uint32_t sb = smem_u32(smem);
    const uint32_t mbs0 = sb, mbs1 = sb + 8, mbs2 = sb + 16;
    float* sbhn = (float*)(smem + 32);
    __half* whi = (__half*)(smem + W_HI_OFF);
    __half* wlo = (__half*)(smem + W_LO_OFF);

    if (tid == 0) { mbar_init(mbs0, 1); mbar_init(mbs1, 1); mbar_init(mbs2, 1); }

    // one-time weight slice load (96KB)
    {
        const __half* srcH = g_Wg_hi + (size_t)jb * 24 * HH;
        const __half* srcL = g_Wg_lo + (size_t)jb * 24 * HH;
        for (int u = tid; u < 3072; u += 128) {
            int c = u >> 7, q = u & 127;
            cp16(whi + c * WP + q * 8, srcH + c * HH + q * 8);
            cp16(wlo + c * WP + q * 8, srcL + c * HH + q * 8);
        }
    }
    if (tid < 8) sbhn[tid] = bhn[jb * 8 + tid];
    cp_commit();
    asm volatile("cp.async.wait_group 0;\n" ::: "memory");
    __syncthreads();

    const uint32_t sA = sb + A_OFF;
    const int a_row = (w << 4) + (lane & 15);
    const int a_k   = (lane >> 4) << 3;
    const int b_col = lane & 7;
    const int b_k   = ((lane >> 3) & 1) << 3;
    // packed B ldsm4: lanes 0-15 read whi, lanes 16-31 read wlo (same row pattern)
    const uint32_t s_wb = (lane & 16) ? (sb + W_LO_OFF) : (sb + W_HI_OFF);
    const int cb = jb >> 5;            // megachunk this CTA produces into
    const int b0 = (w << 4) + (lane >> 2);
    const int b1 = b0 + 8;
    const int jc0 = jb * 8 + ((lane & 3) << 1);   // cols for e even (e&1==0)

    int ph0 = 0, ph1 = 0, ph2 = 0;

    for (int t = 0; t < SS; t++) {
        const unsigned char* hbase = g_h + (size_t)t * STEP_BYTES;

        if (tid == 0) {
            // poll producers of megachunks 0..2, then issue hi-half bulk loads
#pragma unroll
            for (int c = 0; c < 3; c++) {
                if (t > 0) wait32(&g_bar[t * 4 + c]);
                const uint32_t mb = (c == 0) ? mbs0 : (c == 1) ? mbs1 : mbs2;
                mbar_expect(mb, MEGA_BYTES);
                bulk_g2s(sA + c * MEGA_BYTES, hbase + (size_t)(2 * c) * CHUNK_BYTES,
                         HALF_CHUNK, mb);
                bulk_g2s(sA + c * MEGA_BYTES + HALF_CHUNK,
                         hbase + (size_t)(2 * c + 1) * CHUNK_BYTES, HALF_CHUNK, mb);
            }
        }

        // hoisted epilogue inputs: tokens, P values, h_old (hidden under mainloop)
        const int tok0 = inputs[b0 * SS + t];
        const int tok1 = inputs[b1 * SS + t];
        float Pr[4], Pz[4], Pn[4], hold[4];
#pragma unroll
        for (int e = 0; e < 4; e++) {
            const int b = (e & 2) ? b1 : b0;
            const int tok = (e & 2) ? tok1 : tok0;
            const int j = jc0 + (e & 1);
            const float* Pp = g_P + (size_t)tok * (3 * HH) + j;
            Pr[e] = Pp[0];
            Pz[e] = Pp[HH];
            Pn[e] = Pp[2 * HH];
            const size_t hao = haddr(t, b, j);
            hold[e] = __half2float(*(const __half*)(g_h + hao)) +
                      __half2float(*(const __half*)(g_h + hao + HALF_CHUNK));
        }

        float accR[4] = {0.f, 0.f, 0.f, 0.f};
        float accZ[4] = {0.f, 0.f, 0.f, 0.f};
        float accN[4] = {0.f, 0.f, 0.f, 0.f};

#pragma unroll
        for (int kc = 0; kc < 4; kc++) {
            const int buf = (kc < 3) ? kc : 0;
            const uint32_t mb = (buf == 0) ? mbs0 : (buf == 1) ? mbs1 : mbs2;
            int* php = (buf == 0) ? &ph0 : (buf == 1) ? &ph1 : &ph2;
            mbar_wait(mb, *php);
            *php ^= 1;

            const uint32_t aBase = sA + buf * MEGA_BYTES + a_row * ROWB + a_k * 2;
            const uint32_t bBase = s_wb + (uint32_t)(b_col * WP + kc * 256 + b_k) * 2;
#pragma unroll
            for (int ks = 0; ks < 16; ks++) {
                const int k0 = (ks & 7) * 16;
                const uint32_t aoff = (uint32_t)((ks >> 3) * HALF_CHUNK + k0 * 2);
                uint32_t a[4];
                ldsm4(a, aBase + aoff);
                uint32_t bR[4], bZ[4], bN[4];
                const uint32_t koff = (uint32_t)(ks * 16) * 2;
                ldsm4(bR, bBase + koff);
                ldsm4(bZ, bBase + (uint32_t)(8 * WP) * 2 + koff);
                ldsm4(bN, bBase + (uint32_t)(16 * WP) * 2 + koff);
                // hi then lo, interleaved accumulators (RAW distance 3)
                mma_f16(accR, a, bR);
                mma_f16(accZ, a, bZ);
                mma_f16(accN, a, bN);
                mma_f16(accR, a, bR + 2);
                mma_f16(accZ, a, bZ + 2);
                mma_f16(accN, a, bN + 2);
            }
            __syncthreads();  // all warps done reading buf
            if (kc == 0 && tid == 0) {
                if (t > 0) wait32(&g_bar[t * 4 + 3]);
                mbar_expect(mb, MEGA_BYTES);
                bulk_g2s(sA, hbase + (size_t)6 * CHUNK_BYTES, HALF_CHUNK, mb);
                bulk_g2s(sA + HALF_CHUNK, hbase + (size_t)7 * CHUNK_BYTES, HALF_CHUNK, mb);
            }
        }

        // --- epilogue: gates + h update, vectorized half2 stores ---
        __half2 oh[2], ol[2];
#pragma unroll
        for (int e = 0; e < 4; e++) {
            const int col = ((lane & 3) << 1) + (e & 1);
            const float r = sigf(Pr[e] + accR[e]);
            const float z = sigf(Pz[e] + accZ[e]);
            const float nv = tanhf(Pn[e] + r * (accN[e] + sbhn[col]));
            const float hn = nv + z * (hold[e] - nv);  // (1-z)*n + z*h
            const __half hi = __float2half_rn(hn);
            const __half lo = __float2half_rn(hn - __half2float(hi));
            if (e & 1) { oh[e >> 1].y = hi; ol[e >> 1].y = lo; }
            else       { oh[e >> 1].x = hi; ol[e >> 1].x = lo; }
        }
        {
            const size_t h0 = haddr(t + 1, b0, jc0);
            const size_t h1 = haddr(t + 1, b1, jc0);
            *(__half2*)(g_h + h0) = oh[0];
            *(__half2*)(g_h + h0 + HALF_CHUNK) = ol[0];
            *(__half2*)(g_h + h1) = oh[1];
            *(__half2*)(g_h + h1 + HALF_CHUNK) = ol[1];
        }

        // --- signal: this CTA's contribution to h_{t+1} megachunk cb is done ---
        __threadfence();
        __syncthreads();
        if (tid == 0) {
            asm volatile("red.release.gpu.global.add.u32 [%0], %1;"
                         ::"l"(&g_bar[(t + 1) * 4 + cb]), "r"(1u) : "memory");
        }
    }
}

// ============================================================================
// carry output: reconstruct h[512] to fp32
// ============================================================================
__global__ void k_carry_out(float* __restrict__ out) {
    int i = blockIdx.x * blockDim.x + threadIdx.x;
    if (i >= BB * HH) return;
    int b = i >> 10, j = i & (HH - 1);
    size_t ha = haddr(SS, b, j);
    out[i] = __half2float(*(const __half*)(g_h + ha)) +
             __half2float(*(const __half*)(g_h + ha + HALF_CHUNK));
}

// ============================================================================
// logits GEMM: [32768,1024] @ WcT + bc, split-fp16 mma, m64 x n64 per block
// ============================================================================
__global__ void __launch_bounds__(128, 1) k_logits(float* __restrict__ out) {
    extern __shared__ char smem[];
    __half* Ah = (__half*)smem;        // 2*64*HP
    __half* Al = Ah + 2 * 64 * HP;
    __half* Bh = Al + 2 * 64 * HP;
    __half* Bl = Bh + 2 * 64 * HP;

    const int tid = threadIdx.x;
    const int w = tid >> 5, lane = tid & 31;
    const int r0 = blockIdx.x * 64;            // global row block (row = b*512 + t)
    const int bidx = r0 >> 9;                  // batch
    const int t0 = r0 & (SS - 1);              // time offset
    const int o0 = blockIdx.y * 64;

    const __half* srcBh = g_WcT_hi + (size_t)o0 * HH;
    const __half* srcBl = g_WcT_lo + (size_t)o0 * HH;

    auto prefetch = [&](int kc, int buf) {
        for (int u = tid; u < 1024; u += 128) {
            int row = u >> 4, q = u & 15;
            const unsigned char* srcA = g_h + (size_t)(t0 + row + 1) * STEP_BYTES +
                                        (size_t)kc * CHUNK_BYTES + (size_t)bidx * ROWB +
                                        (size_t)q * 16;
            cp16(Ah + buf * (64 * HP) + row * HP + q * 8, srcA);
            cp16(Al + buf * (64 * HP) + row * HP + q * 8, srcA + HALF_CHUNK);
            cp16(Bh + buf * (64 * HP) + row * HP + q * 8,
                 srcBh + (size_t)row * HH + kc * 128 + q * 8);
            cp16(Bl + buf * (64 * HP) + row * HP + q * 8,
                 srcBl + (size_t)row * HH + kc * 128 + q * 8);
        }
        cp_commit();
    };

    const uint32_t sAh = (uint32_t)__cvta_generic_to_shared(Ah);
    const uint32_t sAl = (uint32_t)__cvta_generic_to_shared(Al);
    const uint32_t sBh = (uint32_t)__cvta_generic_to_shared(Bh);
    const uint32_t sBl = (uint32_t)__cvta_generic_to_shared(Bl);

    const int a_rl = lane & 15;
    const int a_k  = (lane >> 4) << 3;
    const int b_cl = lane & 7;
    const int b_k  = ((lane >> 3) & 1) << 3;

    float acc[4][2][4];
#pragma unroll
    for (int mt = 0; mt < 4; mt++)
#pragma unroll
        for (int nt = 0; nt < 2; nt++)
#pragma unroll
            for (int e = 0; e < 4; e++) acc[mt][nt][e] = 0.f;

    prefetch(0, 0);
    for (int kc = 0; kc < 8; kc++) {
        if (kc < 7) {
            prefetch(kc + 1, (kc + 1) & 1);
            asm volatile("cp.async.wait_group 1;\n");
        } else {
            asm volatile("cp.async.wait_group 0;\n");
        }
        __syncthreads();
        const int buf = kc & 1;
#pragma unroll
        for (int ks = 0; ks < 8; ks++) {
            const int k0 = ks * 16;
            uint32_t ah[4][4], al[4][4];
#pragma unroll
            for (int mt = 0; mt < 4; mt++) {
                const uint32_t ao =
                    (uint32_t)(buf * (64 * HP) + (mt * 16 + a_rl) * HP + k0 + a_k) * 2;
                ldsm4(ah[mt], sAh + ao);
                ldsm4(al[mt], sAl + ao);
            }
#pragma unroll
            for (int nt = 0; nt < 2; nt++) {
                const int colg = (w * 2 + nt) * 8 + b_cl;
                const uint32_t bo = (uint32_t)(buf * (64 * HP) + colg * HP + k0 + b_k) * 2;
                uint32_t bh2[2], bl2[2];
                ldsm2(bh2, sBh + bo);
                ldsm2(bl2, sBl + bo);
#pragma unroll
                for (int mt = 0; mt < 4; mt++) {
                    mma_f16(acc[mt][nt], ah[mt], bh2);
                    mma_f16(acc[mt][nt], al[mt], bh2);
                    mma_f16(acc[mt][nt], ah[mt], bl2);
                }
            }
        }
        __syncthreads();
    }

#pragma unroll
    for (int mt = 0; mt < 4; mt++)
#pragma unroll
        for (int nt = 0; nt < 2; nt++)
#pragma unroll
            for (int e = 0; e < 4; e++) {
                const int row = r0 + mt * 16 + (lane >> 2) + ((e >> 1) << 3);
                const int o = o0 + (w * 2 + nt) * 8 + ((lane & 3) << 1) + (e & 1);
                out[(size_t)row * OO + o] = acc[mt][nt][e] + g_bc[o];
            }
}

// ============================================================================
// launcher — k_gru is the 4th launch (ncu's profiled slot)
// ============================================================================
extern "C" void kernel_launch(void* const* d_in, const int* in_sizes, int n_in,
                              void* d_out, int out_size) {
    const int*   inputs = (const int*)d_in[0];
    const float* carry  = (const float*)d_in[1];
    const float* emb    = (const float*)d_in[2];
    const float* Wir    = (const float*)d_in[3];
    const float* bir    = (const float*)d_in[4];
    const float* Whr    = (const float*)d_in[5];
    const float* Wiz    = (const float*)d_in[6];
    const float* biz    = (const float*)d_in[7];
    const float* Whz    = (const float*)d_in[8];
    const float* Win    = (const float*)d_in[9];
    const float* bin_   = (const float*)d_in[10];
    const float* Whn    = (const float*)d_in[11];
    const float* bhn    = (const float*)d_in[12];
    const float* Wh     = (const float*)d_in[13];
    const float* bh     = (const float*)d_in[14];
    const float* Wo     = (const float*)d_in[15];
    const float* bo     = (const float*)d_in[16];

    float* out = (float*)d_out;

    const int LOG_SMEM = 4 * (2 * 64 * HP) * 2;  // 139264
    cudaFuncSetAttribute(k_gru, cudaFuncAttributeMaxDynamicSharedMemorySize, GRU_SMEM_BYTES);
    cudaFuncSetAttribute(k_logits, cudaFuncAttributeMaxDynamicSharedMemorySize, LOG_SMEM);

    k_init0<<<(BB * HH + (SS + 1) * 4 + 255) / 256, 256>>>(carry);                 // 1
    k_pack_w<<<(NBLK * 24 * HH + 255) / 256, 256>>>(Whr, Whz, Whn);                // 2
    k_build_P<<<(VV * 3 * HH + 255) / 256, 256>>>(emb, Wir, bir, Wiz, biz, Win, bin_); // 3
    k_gru<<<NBLK, 128, GRU_SMEM_BYTES>>>(inputs, bhn);                             // 4
    k_carry_out<<<(BB * HH + 255) / 256, 256>>>(out);                              // 5
    k_build_Wc<<<(HH * OO + 255) / 256, 256>>>(Wh, bh, Wo, bo);                    // 6
    dim3 lgrid(BB * SS / 64, OO / 64);  // (512, 2)
    k_logits<<<lgrid, 128, LOG_SMEM>>>(out + (size_t)BB * HH);                     // 7
}